// round 5
// baseline (speedup 1.0000x reference)
#include <cuda_runtime.h>
#include <cuda_bf16.h>

// Problem constants
#define BB   8
#define LL   4096
#define DD   512
#define DFF  2048
#define HH   8
#define DH   64
#define SK   128
#define UU   128
#define ROWS (BB*LL)        // 32768
#define BHN  (BB*HH)        // 64
#define KSPLIT 8

// ---------------- scratch (device globals: no allocation allowed) ----------
__device__ float g_Q[ROWS*DD];
__device__ float g_K[ROWS*DD];
__device__ float g_V[ROWS*DD];
__device__ float g_M[BHN*LL];
__device__ int   g_topidx[BHN*UU];
__device__ float g_scores[(size_t)BHN*UU*LL];     // 33.5M floats
__device__ float g_meanV[BHN*DH];
__device__ float g_ctx[ROWS*DD];
__device__ float g_ctxpart[(size_t)BHN*KSPLIT*UU*DH];
__device__ float g_res1[ROWS*DD];
__device__ float g_x1[ROWS*DD];
__device__ float g_ffh[(size_t)ROWS*DFF];         // 67M floats
__device__ float g_res2[ROWS*DD];

// ---------------- generic SGEMM: C = A(MxK) * B(KxN) + bias, opt relu/resid
__global__ __launch_bounds__(256)
void sgemm_kernel(const float* __restrict__ A, const float* __restrict__ B,
                  const float* __restrict__ bias, const float* __restrict__ resid,
                  float* __restrict__ C, int M, int N, int K, int doRelu)
{
    __shared__ float As[8][132];   // k x m (padded)
    __shared__ float Bs[8][128];   // k x n
    const int tid = threadIdx.x;
    const int rowBase = blockIdx.y * 128;
    const int colBase = blockIdx.x * 128;

    const int ar = tid >> 1, ac = (tid & 1) * 4;          // A tile load map
    const int br = tid >> 5, bc = (tid & 31) * 4;         // B tile load map
    const float* Aptr = A + (size_t)(rowBase + ar) * K + ac;
    const float* Bptr = B + (size_t)br * N + colBase + bc;

    float4 aReg = *(const float4*)Aptr;
    float4 bReg = *(const float4*)Bptr;

    float acc[8][8];
    #pragma unroll
    for (int i = 0; i < 8; i++)
        #pragma unroll
        for (int j = 0; j < 8; j++) acc[i][j] = 0.f;

    const int ty = tid >> 4, tx = tid & 15;
    const int nIter = K >> 3;

    for (int it = 0; it < nIter; ++it) {
        As[ac+0][ar] = aReg.x; As[ac+1][ar] = aReg.y;
        As[ac+2][ar] = aReg.z; As[ac+3][ar] = aReg.w;
        *(float4*)&Bs[br][bc] = bReg;
        __syncthreads();
        if (it + 1 < nIter) {
            aReg = *(const float4*)(Aptr + (size_t)(it+1)*8);
            bReg = *(const float4*)(Bptr + (size_t)(it+1)*8*N);
        }
        #pragma unroll
        for (int k = 0; k < 8; k++) {
            float a[8], b[8];
            *(float4*)&a[0] = *(const float4*)&As[k][ty*8];
            *(float4*)&a[4] = *(const float4*)&As[k][ty*8+4];
            *(float4*)&b[0] = *(const float4*)&Bs[k][tx*8];
            *(float4*)&b[4] = *(const float4*)&Bs[k][tx*8+4];
            #pragma unroll
            for (int i = 0; i < 8; i++)
                #pragma unroll
                for (int j = 0; j < 8; j++)
                    acc[i][j] = fmaf(a[i], b[j], acc[i][j]);
        }
        __syncthreads();
    }

    #pragma unroll
    for (int i = 0; i < 8; i++) {
        const int row = rowBase + ty*8 + i;
        #pragma unroll
        for (int j = 0; j < 8; j += 4) {
            const int col = colBase + tx*8 + j;
            float4 c;
            c.x = acc[i][j+0] + bias[col+0];
            c.y = acc[i][j+1] + bias[col+1];
            c.z = acc[i][j+2] + bias[col+2];
            c.w = acc[i][j+3] + bias[col+3];
            if (doRelu) {
                c.x = fmaxf(c.x, 0.f); c.y = fmaxf(c.y, 0.f);
                c.z = fmaxf(c.z, 0.f); c.w = fmaxf(c.w, 0.f);
            }
            if (resid) {
                const float4 r = *(const float4*)&resid[(size_t)row*N + col];
                c.x += r.x; c.y += r.y; c.z += r.z; c.w += r.w;
            }
            *(float4*)&C[(size_t)row*N + col] = c;
        }
    }
}

// ---------------- sampling metric: M[b,h,l] = max_s(QK_s) - mean_s(QK_s) ----
__global__ __launch_bounds__(128)
void sampm_kernel(const float* __restrict__ Q, const float* __restrict__ Kmat,
                  const long long* __restrict__ sidx, float* __restrict__ Mout)
{
    const int bh = blockIdx.y, b = bh >> 3, h = bh & 7;
    const int lt = blockIdx.x;
    __shared__ float Ks[SK][DH];
    const int tid = threadIdx.x;
    for (int i = tid; i < SK*16; i += 128) {
        const int s = i >> 4, c4 = (i & 15) * 4;
        const int row = (int)sidx[s];
        *(float4*)&Ks[s][c4] =
            *(const float4*)&Kmat[((size_t)(b*LL + row))*DD + h*DH + c4];
    }
    __syncthreads();
    const int l = lt*128 + tid;
    float4 q[16];
    const float* qp = &Q[((size_t)(b*LL + l))*DD + h*DH];
    #pragma unroll
    for (int i = 0; i < 16; i++) q[i] = *(const float4*)(qp + i*4);
    float mx = -1e30f, sm = 0.f;
    for (int s = 0; s < SK; s++) {
        float a = 0.f;
        #pragma unroll
        for (int i = 0; i < 16; i++) {
            const float4 k4 = *(const float4*)&Ks[s][i*4];
            a = fmaf(q[i].x, k4.x, a); a = fmaf(q[i].y, k4.y, a);
            a = fmaf(q[i].z, k4.z, a); a = fmaf(q[i].w, k4.w, a);
        }
        mx = fmaxf(mx, a); sm += a;
    }
    Mout[(size_t)bh*LL + l] = mx - sm * (1.0f/128.0f);
}

// ---------------- top-128 per (b,h): iterative argmax -----------------------
__global__ __launch_bounds__(256)
void topk_kernel(const float* __restrict__ Mvals, int* __restrict__ topidx)
{
    const int bh = blockIdx.x;
    __shared__ float vals[LL];
    __shared__ float rv[256];
    __shared__ int   ri[256];
    const int tid = threadIdx.x;
    for (int i = tid; i < LL; i += 256) vals[i] = Mvals[(size_t)bh*LL + i];
    __syncthreads();
    for (int it = 0; it < UU; ++it) {
        float best = -1e38f; int bi = 1 << 30;
        for (int j = tid; j < LL; j += 256) {
            const float v = vals[j];
            if (v > best) { best = v; bi = j; }
        }
        rv[tid] = best; ri[tid] = bi;
        __syncthreads();
        for (int s = 128; s > 0; s >>= 1) {
            if (tid < s) {
                const float v2 = rv[tid+s]; const int i2 = ri[tid+s];
                if (v2 > rv[tid] || (v2 == rv[tid] && i2 < ri[tid])) {
                    rv[tid] = v2; ri[tid] = i2;
                }
            }
            __syncthreads();
        }
        if (tid == 0) { topidx[bh*UU + it] = ri[0]; vals[ri[0]] = -1e38f; }
        __syncthreads();
    }
}

// ---------------- scores = gather(Q,top) @ K^T * scale ----------------------
__global__ __launch_bounds__(256)
void scores_kernel(const float* __restrict__ Q, const float* __restrict__ Kmat,
                   const int* __restrict__ topidx, float* __restrict__ scores)
{
    const int bh = blockIdx.y, b = bh >> 3, h = bh & 7;
    const int lt = blockIdx.x;                 // 0..31
    __shared__ float As[32][132];              // k x u
    __shared__ float Bs[32][132];              // k x l
    const int tid = threadIdx.x;
    const int ty = tid >> 4, tx = tid & 15;
    float acc[8][8];
    #pragma unroll
    for (int i = 0; i < 8; i++)
        #pragma unroll
        for (int j = 0; j < 8; j++) acc[i][j] = 0.f;

    for (int kc = 0; kc < DH; kc += 32) {
        for (int i = tid; i < 128*8; i += 256) {
            const int u = i >> 3, c4 = (i & 7) * 4;
            const int row = topidx[bh*UU + u];
            const float4 v = *(const float4*)
                &Q[((size_t)(b*LL + row))*DD + h*DH + kc + c4];
            As[c4+0][u] = v.x; As[c4+1][u] = v.y; As[c4+2][u] = v.z; As[c4+3][u] = v.w;
        }
        for (int i = tid; i < 128*8; i += 256) {
            const int l = i >> 3, c4 = (i & 7) * 4;
            const float4 v = *(const float4*)
                &Kmat[((size_t)(b*LL + lt*128 + l))*DD + h*DH + kc + c4];
            Bs[c4+0][l] = v.x; Bs[c4+1][l] = v.y; Bs[c4+2][l] = v.z; Bs[c4+3][l] = v.w;
        }
        __syncthreads();
        #pragma unroll
        for (int k = 0; k < 32; k++) {
            float a[8], bb2[8];
            *(float4*)&a[0]  = *(const float4*)&As[k][ty*8];
            *(float4*)&a[4]  = *(const float4*)&As[k][ty*8+4];
            *(float4*)&bb2[0] = *(const float4*)&Bs[k][tx*8];
            *(float4*)&bb2[4] = *(const float4*)&Bs[k][tx*8+4];
            #pragma unroll
            for (int i = 0; i < 8; i++)
                #pragma unroll
                for (int j = 0; j < 8; j++)
                    acc[i][j] = fmaf(a[i], bb2[j], acc[i][j]);
        }
        __syncthreads();
    }
    const float scale = 0.125f;   // 1/sqrt(64)
    #pragma unroll
    for (int i = 0; i < 8; i++) {
        const int u = ty*8 + i;
        float* outp = scores + ((size_t)bh*UU + u)*LL + lt*128 + tx*8;
        #pragma unroll
        for (int j = 0; j < 8; j += 4) {
            float4 c;
            c.x = acc[i][j+0]*scale; c.y = acc[i][j+1]*scale;
            c.z = acc[i][j+2]*scale; c.w = acc[i][j+3]*scale;
            *(float4*)(outp + j) = c;
        }
    }
}

// ---------------- softmax over L per (bh,u) row -----------------------------
__global__ __launch_bounds__(256)
void softmax_kernel(float* __restrict__ scores)
{
    const size_t row = blockIdx.x;
    float* p = scores + row * LL;
    __shared__ float red[256];
    const int tid = threadIdx.x;
    float4 v[4];
    float mx = -1e30f;
    #pragma unroll
    for (int i = 0; i < 4; i++) {
        v[i] = *(const float4*)&p[tid*4 + i*1024];
        mx = fmaxf(mx, fmaxf(fmaxf(v[i].x, v[i].y), fmaxf(v[i].z, v[i].w)));
    }
    red[tid] = mx; __syncthreads();
    for (int s = 128; s > 0; s >>= 1) {
        if (tid < s) red[tid] = fmaxf(red[tid], red[tid+s]);
        __syncthreads();
    }
    mx = red[0]; __syncthreads();
    float sum = 0.f;
    #pragma unroll
    for (int i = 0; i < 4; i++) {
        v[i].x = __expf(v[i].x - mx); v[i].y = __expf(v[i].y - mx);
        v[i].z = __expf(v[i].z - mx); v[i].w = __expf(v[i].w - mx);
        sum += v[i].x + v[i].y + v[i].z + v[i].w;
    }
    red[tid] = sum; __syncthreads();
    for (int s = 128; s > 0; s >>= 1) {
        if (tid < s) red[tid] += red[tid+s];
        __syncthreads();
    }
    const float inv = 1.0f / red[0];
    #pragma unroll
    for (int i = 0; i < 4; i++) {
        v[i].x *= inv; v[i].y *= inv; v[i].z *= inv; v[i].w *= inv;
        *(float4*)&p[tid*4 + i*1024] = v[i];
    }
}

// ---------------- meanV over L per (b,h) ------------------------------------
__global__ __launch_bounds__(256)
void meanv_kernel(const float* __restrict__ V, float* __restrict__ meanV)
{
    const int bh = blockIdx.x, b = bh >> 3, h = bh & 7;
    __shared__ float sm[4][64];
    const int tid = threadIdx.x;
    const int d = tid & 63, p = tid >> 6;
    float s = 0.f;
    for (int l = p; l < LL; l += 4)
        s += V[((size_t)(b*LL + l))*DD + h*DH + d];
    sm[p][d] = s; __syncthreads();
    if (p == 0)
        meanV[bh*DH + d] = (sm[0][d]+sm[1][d]+sm[2][d]+sm[3][d]) * (1.0f/4096.0f);
}

// ---------------- ctx := broadcast(meanV) -----------------------------------
__global__ void fill_ctx(const float* __restrict__ meanV, float* __restrict__ ctx)
{
    const size_t i = (size_t)blockIdx.x * blockDim.x + threadIdx.x;
    if (i >= (size_t)ROWS*DD) return;
    const int d = (int)(i & 511);
    const int b = (int)(i >> 21);
    const int h = d >> 6, dd = d & 63;
    ctx[i] = meanV[(b*HH + h)*DH + dd];
}

// ---------------- partial ctx_top = attn @ V (split-K) ----------------------
__global__ __launch_bounds__(256)
void ctxpart_kernel(const float* __restrict__ scores, const float* __restrict__ V,
                    float* __restrict__ part)
{
    const int bh = blockIdx.x, ks = blockIdx.y;
    const int b = bh >> 3, h = bh & 7;
    __shared__ float As[8][132];   // k x u
    __shared__ float Bs[8][68];    // k x n
    const int tid = threadIdx.x;
    const int ty = tid >> 4, tx = tid & 15;   // u = ty*8.., n = tx*4..
    float acc[8][4];
    #pragma unroll
    for (int i = 0; i < 8; i++)
        #pragma unroll
        for (int j = 0; j < 4; j++) acc[i][j] = 0.f;

    const float* Arow = scores + (size_t)bh*UU*LL;   // [u][l], ld=LL
    const int kbase0 = ks * (LL / KSPLIT);           // 512 per split
    const int ar = tid >> 1, ac = (tid & 1) * 4;
    const int kr = (tid*2) >> 6, cc = (tid*2) & 63;

    for (int it = 0; it < (LL/KSPLIT)/8; ++it) {
        const int kb = kbase0 + it*8;
        const float4 av = *(const float4*)&Arow[(size_t)ar*LL + kb + ac];
        As[ac+0][ar] = av.x; As[ac+1][ar] = av.y;
        As[ac+2][ar] = av.z; As[ac+3][ar] = av.w;
        const float2 bv = *(const float2*)
            &V[((size_t)(b*LL) + kb + kr)*DD + h*DH + cc];
        Bs[kr][cc] = bv.x; Bs[kr][cc+1] = bv.y;
        __syncthreads();
        #pragma unroll
        for (int k = 0; k < 8; k++) {
            float a[8];
            *(float4*)&a[0] = *(const float4*)&As[k][ty*8];
            *(float4*)&a[4] = *(const float4*)&As[k][ty*8+4];
            const float4 b4 = *(const float4*)&Bs[k][tx*4];
            #pragma unroll
            for (int i = 0; i < 8; i++) {
                acc[i][0] = fmaf(a[i], b4.x, acc[i][0]);
                acc[i][1] = fmaf(a[i], b4.y, acc[i][1]);
                acc[i][2] = fmaf(a[i], b4.z, acc[i][2]);
                acc[i][3] = fmaf(a[i], b4.w, acc[i][3]);
            }
        }
        __syncthreads();
    }
    #pragma unroll
    for (int i = 0; i < 8; i++) {
        const int u = ty*8 + i;
        float4 c; c.x = acc[i][0]; c.y = acc[i][1]; c.z = acc[i][2]; c.w = acc[i][3];
        *(float4*)&part[(((size_t)bh*KSPLIT + ks)*UU + u)*DH + tx*4] = c;
    }
}

// ---------------- combine split-K + scatter into ctx ------------------------
__global__ void combine_scatter(const float* __restrict__ part,
                                const int* __restrict__ topidx,
                                float* __restrict__ ctx)
{
    const int idx = blockIdx.x * blockDim.x + threadIdx.x;  // BHN*UU*DH
    if (idx >= BHN*UU*DH) return;
    const int n = idx & 63, u = (idx >> 6) & 127, bh = idx >> 13;
    float s = 0.f;
    #pragma unroll
    for (int ks = 0; ks < KSPLIT; ks++)
        s += part[(((size_t)bh*KSPLIT + ks)*UU + u)*DH + n];
    const int b = bh >> 3, h = bh & 7;
    const int row = topidx[bh*UU + u];
    ctx[((size_t)(b*LL + row))*DD + h*DH + n] = s;
}

// ---------------- layernorm over D=512 rows ---------------------------------
__global__ __launch_bounds__(128)
void ln_kernel(const float* __restrict__ X, const float* __restrict__ g,
               const float* __restrict__ bb, float* __restrict__ Y)
{
    const size_t row = blockIdx.x;
    const float* x = X + row * DD;
    const int tid = threadIdx.x;
    __shared__ float red[128];
    const float4 v = *(const float4*)&x[tid*4];
    red[tid] = v.x + v.y + v.z + v.w; __syncthreads();
    for (int s = 64; s > 0; s >>= 1) {
        if (tid < s) red[tid] += red[tid+s];
        __syncthreads();
    }
    const float m = red[0] * (1.0f/512.0f);
    __syncthreads();
    const float dx = v.x - m, dy = v.y - m, dz = v.z - m, dw = v.w - m;
    red[tid] = dx*dx + dy*dy + dz*dz + dw*dw; __syncthreads();
    for (int s = 64; s > 0; s >>= 1) {
        if (tid < s) red[tid] += red[tid+s];
        __syncthreads();
    }
    const float var = red[0] * (1.0f/512.0f);
    const float rs = rsqrtf(var + 1e-6f);
    const float4 gv = *(const float4*)&g[tid*4];
    const float4 bv = *(const float4*)&bb[tid*4];
    float4 o;
    o.x = dx*rs*gv.x + bv.x; o.y = dy*rs*gv.y + bv.y;
    o.z = dz*rs*gv.z + bv.z; o.w = dw*rs*gv.w + bv.w;
    *(float4*)&Y[row*DD + tid*4] = o;
}

// ---------------- driver -----------------------------------------------------
extern "C" void kernel_launch(void* const* d_in, const int* in_sizes, int n_in,
                              void* d_out, int out_size)
{
    const float* x    = (const float*)d_in[0];
    const float* Wq   = (const float*)d_in[1];
    const float* bq   = (const float*)d_in[2];
    const float* Wk   = (const float*)d_in[3];
    const float* bk   = (const float*)d_in[4];
    const float* Wv   = (const float*)d_in[5];
    const float* bv   = (const float*)d_in[6];
    const float* Wo   = (const float*)d_in[7];
    const float* bo   = (const float*)d_in[8];
    const float* g1   = (const float*)d_in[9];
    const float* b1   = (const float*)d_in[10];
    const float* W1f  = (const float*)d_in[11];
    const float* b1f  = (const float*)d_in[12];
    const float* W2f  = (const float*)d_in[13];
    const float* b2f  = (const float*)d_in[14];
    const float* g2   = (const float*)d_in[15];
    const float* b2   = (const float*)d_in[16];
    const long long* sidx = (const long long*)d_in[17];
    float* out = (float*)d_out;

    float *Qb,*Kb,*Vb,*Mb,*Sc,*mv,*ctx,*cp,*r1,*x1,*fh,*r2;
    int* ti;
    cudaGetSymbolAddress((void**)&Qb,  g_Q);
    cudaGetSymbolAddress((void**)&Kb,  g_K);
    cudaGetSymbolAddress((void**)&Vb,  g_V);
    cudaGetSymbolAddress((void**)&Mb,  g_M);
    cudaGetSymbolAddress((void**)&ti,  g_topidx);
    cudaGetSymbolAddress((void**)&Sc,  g_scores);
    cudaGetSymbolAddress((void**)&mv,  g_meanV);
    cudaGetSymbolAddress((void**)&ctx, g_ctx);
    cudaGetSymbolAddress((void**)&cp,  g_ctxpart);
    cudaGetSymbolAddress((void**)&r1,  g_res1);
    cudaGetSymbolAddress((void**)&x1,  g_x1);
    cudaGetSymbolAddress((void**)&fh,  g_ffh);
    cudaGetSymbolAddress((void**)&r2,  g_res2);

    // 1-3: Q/K/V projections
    sgemm_kernel<<<dim3(DD/128, ROWS/128), 256>>>(x, Wq, bq, nullptr, Qb, ROWS, DD, DD, 0);
    sgemm_kernel<<<dim3(DD/128, ROWS/128), 256>>>(x, Wk, bk, nullptr, Kb, ROWS, DD, DD, 0);
    sgemm_kernel<<<dim3(DD/128, ROWS/128), 256>>>(x, Wv, bv, nullptr, Vb, ROWS, DD, DD, 0);
    // 4: sampling metric M
    sampm_kernel<<<dim3(LL/128, BHN), 128>>>(Qb, Kb, sidx, Mb);
    // 5: top-128 indices
    topk_kernel<<<BHN, 256>>>(Mb, ti);
    // 6: scores (gathered Q_top @ K^T * scale)
    scores_kernel<<<dim3(LL/128, BHN), 256>>>(Qb, Kb, ti, Sc);
    // 7: softmax
    softmax_kernel<<<BHN*UU, 256>>>(Sc);
    // 8-9: meanV + broadcast fill
    meanv_kernel<<<BHN, 256>>>(Vb, mv);
    fill_ctx<<<(ROWS*DD + 255)/256, 256>>>(mv, ctx);
    // 10-11: attn @ V (split-K) + combine/scatter
    ctxpart_kernel<<<dim3(BHN, KSPLIT), 256>>>(Sc, Vb, cp);
    combine_scatter<<<(BHN*UU*DH + 255)/256, 256>>>(cp, ti, ctx);
    // 12: output projection + residual x
    sgemm_kernel<<<dim3(DD/128, ROWS/128), 256>>>(ctx, Wo, bo, x, r1, ROWS, DD, DD, 0);
    // 13: LN1
    ln_kernel<<<ROWS, 128>>>(r1, g1, b1, x1);
    // 14: FFN1 + ReLU
    sgemm_kernel<<<dim3(DFF/128, ROWS/128), 256>>>(x1, W1f, b1f, nullptr, fh, ROWS, DFF, DD, 1);
    // 15: FFN2 + residual x1
    sgemm_kernel<<<dim3(DD/128, ROWS/128), 256>>>(fh, W2f, b2f, x1, r2, ROWS, DD, DFF, 0);
    // 16: LN2 -> output
    ln_kernel<<<ROWS, 128>>>(r2, g2, b2, out);
}

// round 7
// speedup vs baseline: 1.5964x; 1.5964x over previous
#include <cuda_runtime.h>
#include <cuda_bf16.h>
#include <cstdint>

// Problem constants
#define BB   8
#define LL   4096
#define DD   512
#define DFF  2048
#define HH   8
#define DH   64
#define SK   128
#define UU   128
#define ROWS (BB*LL)        // 32768
#define BHN  (BB*HH)        // 64
#define KSPLIT 8

// ---------------- scratch (device globals: no allocation allowed) ----------
__device__ float g_Q[ROWS*DD];
__device__ float g_K[ROWS*DD];
__device__ float g_V[ROWS*DD];
__device__ float g_M[BHN*LL];
__device__ int   g_topidx[BHN*UU];
__device__ float g_scores[(size_t)BHN*UU*LL];     // 33.5M floats
__device__ float g_meanV[BHN*DH];
__device__ float g_ctx[ROWS*DD];
__device__ float g_ctxpart[(size_t)BHN*KSPLIT*UU*DH];
__device__ float g_res1[ROWS*DD];
__device__ float g_x1[ROWS*DD];
__device__ float g_ffh[(size_t)ROWS*DFF];         // 67M floats
__device__ float g_res2[ROWS*DD];

// ---------------- tf32 helpers ---------------------------------------------
__device__ __forceinline__ uint32_t f2tf(float x) {
    uint32_t u;
    asm("cvt.rna.tf32.f32 %0, %1;" : "=r"(u) : "f"(x));
    return u;
}

__device__ __forceinline__ void mma_tf32(float* c,
    uint32_t a0, uint32_t a1, uint32_t a2, uint32_t a3,
    uint32_t b0, uint32_t b1)
{
    asm volatile(
        "mma.sync.aligned.m16n8k8.row.col.f32.tf32.tf32.f32 "
        "{%0,%1,%2,%3},{%4,%5,%6,%7},{%8,%9},{%0,%1,%2,%3};"
        : "+f"(c[0]), "+f"(c[1]), "+f"(c[2]), "+f"(c[3])
        : "r"(a0), "r"(a1), "r"(a2), "r"(a3), "r"(b0), "r"(b1));
}

// ---------------- tf32 tensor-core GEMM: C = A(MxK)@B(KxN) + bias ----------
// optional relu and/or residual add. 128x128 tile, BK=16, 256 threads.
// Warp layout: 8 warps as 2 (M) x 4 (N); warp tile 64x32 via m16n8k8.
__global__ __launch_bounds__(256)
void tf32_gemm_kernel(const float* __restrict__ A, const float* __restrict__ B,
                      const float* __restrict__ bias, const float* __restrict__ resid,
                      float* __restrict__ C, int M, int N, int K, int doRelu)
{
    // smA: per k8-half s, per row m, 4 pairs (k = s*8+j, s*8+j+4), pitch 5 (pad)
    __shared__ uint2    smA[2][128][5];
    __shared__ uint32_t smB[16][132];

    const int tid  = threadIdx.x;
    const int warp = tid >> 5, lane = tid & 31;
    const int g = lane >> 2, j = lane & 3;
    const int warpM = (warp >> 2) * 64;
    const int warpN = (warp & 3) * 32;
    const int rowBase = blockIdx.y * 128;
    const int colBase = blockIdx.x * 128;

    // global A load map: thread -> (row am, k-half as)
    const int am = tid >> 1, as = tid & 1;
    const float* Ap = A + (size_t)(rowBase + am) * K + as * 8;
    // global B load map: thread -> (k-row bk, 8 cols at bn)
    const int bk = tid >> 4, bn = (tid & 15) * 8;
    const float* Bp = B + (size_t)bk * N + colBase + bn;

    float4 ag0 = *(const float4*)(Ap);
    float4 ag1 = *(const float4*)(Ap + 4);
    float4 bg0 = *(const float4*)(Bp);
    float4 bg1 = *(const float4*)(Bp + 4);

    float acc[4][4][4];
    #pragma unroll
    for (int mi = 0; mi < 4; mi++)
        #pragma unroll
        for (int nf = 0; nf < 4; nf++)
            #pragma unroll
            for (int q = 0; q < 4; q++) acc[mi][nf][q] = 0.f;

    const int nIter = K >> 4;
    for (int it = 0; it < nIter; ++it) {
        // store A packed pairs (tf32)
        smA[as][am][0] = make_uint2(f2tf(ag0.x), f2tf(ag1.x));
        smA[as][am][1] = make_uint2(f2tf(ag0.y), f2tf(ag1.y));
        smA[as][am][2] = make_uint2(f2tf(ag0.z), f2tf(ag1.z));
        smA[as][am][3] = make_uint2(f2tf(ag0.w), f2tf(ag1.w));
        // store B k-major (tf32)
        smB[bk][bn+0] = f2tf(bg0.x); smB[bk][bn+1] = f2tf(bg0.y);
        smB[bk][bn+2] = f2tf(bg0.z); smB[bk][bn+3] = f2tf(bg0.w);
        smB[bk][bn+4] = f2tf(bg1.x); smB[bk][bn+5] = f2tf(bg1.y);
        smB[bk][bn+6] = f2tf(bg1.z); smB[bk][bn+7] = f2tf(bg1.w);
        __syncthreads();

        if (it + 1 < nIter) {
            Ap += 16;
            Bp += (size_t)16 * N;
            ag0 = *(const float4*)(Ap);
            ag1 = *(const float4*)(Ap + 4);
            bg0 = *(const float4*)(Bp);
            bg1 = *(const float4*)(Bp + 4);
        }

        #pragma unroll
        for (int s = 0; s < 2; ++s) {
            uint2 afr[4][2];
            uint32_t bfr[4][2];
            #pragma unroll
            for (int mi = 0; mi < 4; mi++) {
                afr[mi][0] = smA[s][warpM + mi*16 + g    ][j];
                afr[mi][1] = smA[s][warpM + mi*16 + g + 8][j];
            }
            #pragma unroll
            for (int nf = 0; nf < 4; nf++) {
                bfr[nf][0] = smB[s*8 + j    ][warpN + nf*8 + g];
                bfr[nf][1] = smB[s*8 + j + 4][warpN + nf*8 + g];
            }
            #pragma unroll
            for (int mi = 0; mi < 4; mi++)
                #pragma unroll
                for (int nf = 0; nf < 4; nf++)
                    mma_tf32(acc[mi][nf],
                             afr[mi][0].x, afr[mi][1].x,   // a0 (r,k), a1 (r+8,k)
                             afr[mi][0].y, afr[mi][1].y,   // a2 (r,k+4), a3 (r+8,k+4)
                             bfr[nf][0], bfr[nf][1]);
        }
        __syncthreads();
    }

    // epilogue
    #pragma unroll
    for (int mi = 0; mi < 4; mi++) {
        const int row0 = rowBase + warpM + mi*16 + g;
        const int row1 = row0 + 8;
        #pragma unroll
        for (int nf = 0; nf < 4; nf++) {
            const int col = colBase + warpN + nf*8 + j*2;
            const float2 bv = *(const float2*)&bias[col];
            float2 v0, v1;
            v0.x = acc[mi][nf][0] + bv.x; v0.y = acc[mi][nf][1] + bv.y;
            v1.x = acc[mi][nf][2] + bv.x; v1.y = acc[mi][nf][3] + bv.y;
            if (doRelu) {
                v0.x = fmaxf(v0.x, 0.f); v0.y = fmaxf(v0.y, 0.f);
                v1.x = fmaxf(v1.x, 0.f); v1.y = fmaxf(v1.y, 0.f);
            }
            if (resid) {
                const float2 r0 = *(const float2*)&resid[(size_t)row0*N + col];
                const float2 r1 = *(const float2*)&resid[(size_t)row1*N + col];
                v0.x += r0.x; v0.y += r0.y;
                v1.x += r1.x; v1.y += r1.y;
            }
            *(float2*)&C[(size_t)row0*N + col] = v0;
            *(float2*)&C[(size_t)row1*N + col] = v1;
        }
    }
}

// ---------------- fp32 SGEMM (kept for Q,K — selection-critical) -----------
__global__ __launch_bounds__(256)
void sgemm_kernel(const float* __restrict__ A, const float* __restrict__ B,
                  const float* __restrict__ bias, const float* __restrict__ resid,
                  float* __restrict__ C, int M, int N, int K, int doRelu)
{
    __shared__ float As[8][132];   // k x m (padded)
    __shared__ float Bs[8][128];   // k x n
    const int tid = threadIdx.x;
    const int rowBase = blockIdx.y * 128;
    const int colBase = blockIdx.x * 128;

    const int ar = tid >> 1, ac = (tid & 1) * 4;
    const int br = tid >> 5, bc = (tid & 31) * 4;
    const float* Aptr = A + (size_t)(rowBase + ar) * K + ac;
    const float* Bptr = B + (size_t)br * N + colBase + bc;

    float4 aReg = *(const float4*)Aptr;
    float4 bReg = *(const float4*)Bptr;

    float acc[8][8];
    #pragma unroll
    for (int i = 0; i < 8; i++)
        #pragma unroll
        for (int j = 0; j < 8; j++) acc[i][j] = 0.f;

    const int ty = tid >> 4, tx = tid & 15;
    const int nIter = K >> 3;

    for (int it = 0; it < nIter; ++it) {
        As[ac+0][ar] = aReg.x; As[ac+1][ar] = aReg.y;
        As[ac+2][ar] = aReg.z; As[ac+3][ar] = aReg.w;
        *(float4*)&Bs[br][bc] = bReg;
        __syncthreads();
        if (it + 1 < nIter) {
            aReg = *(const float4*)(Aptr + (size_t)(it+1)*8);
            bReg = *(const float4*)(Bptr + (size_t)(it+1)*8*N);
        }
        #pragma unroll
        for (int k = 0; k < 8; k++) {
            float a[8], b[8];
            *(float4*)&a[0] = *(const float4*)&As[k][ty*8];
            *(float4*)&a[4] = *(const float4*)&As[k][ty*8+4];
            *(float4*)&b[0] = *(const float4*)&Bs[k][tx*8];
            *(float4*)&b[4] = *(const float4*)&Bs[k][tx*8+4];
            #pragma unroll
            for (int i = 0; i < 8; i++)
                #pragma unroll
                for (int j = 0; j < 8; j++)
                    acc[i][j] = fmaf(a[i], b[j], acc[i][j]);
        }
        __syncthreads();
    }

    #pragma unroll
    for (int i = 0; i < 8; i++) {
        const int row = rowBase + ty*8 + i;
        #pragma unroll
        for (int j = 0; j < 8; j += 4) {
            const int col = colBase + tx*8 + j;
            float4 c;
            c.x = acc[i][j+0] + bias[col+0];
            c.y = acc[i][j+1] + bias[col+1];
            c.z = acc[i][j+2] + bias[col+2];
            c.w = acc[i][j+3] + bias[col+3];
            if (doRelu) {
                c.x = fmaxf(c.x, 0.f); c.y = fmaxf(c.y, 0.f);
                c.z = fmaxf(c.z, 0.f); c.w = fmaxf(c.w, 0.f);
            }
            if (resid) {
                const float4 r = *(const float4*)&resid[(size_t)row*N + col];
                c.x += r.x; c.y += r.y; c.z += r.z; c.w += r.w;
            }
            *(float4*)&C[(size_t)row*N + col] = c;
        }
    }
}

// ---------------- sampling metric: M[b,h,l] = max_s(QK_s) - mean_s(QK_s) ----
__global__ __launch_bounds__(128)
void sampm_kernel(const float* __restrict__ Q, const float* __restrict__ Kmat,
                  const long long* __restrict__ sidx, float* __restrict__ Mout)
{
    const int bh = blockIdx.y, b = bh >> 3, h = bh & 7;
    const int lt = blockIdx.x;
    __shared__ float Ks[SK][DH];
    const int tid = threadIdx.x;
    for (int i = tid; i < SK*16; i += 128) {
        const int s = i >> 4, c4 = (i & 15) * 4;
        const int row = (int)sidx[s];
        *(float4*)&Ks[s][c4] =
            *(const float4*)&Kmat[((size_t)(b*LL + row))*DD + h*DH + c4];
    }
    __syncthreads();
    const int l = lt*128 + tid;
    float4 q[16];
    const float* qp = &Q[((size_t)(b*LL + l))*DD + h*DH];
    #pragma unroll
    for (int i = 0; i < 16; i++) q[i] = *(const float4*)(qp + i*4);
    float mx = -1e30f, sm = 0.f;
    for (int s = 0; s < SK; s++) {
        float a = 0.f;
        #pragma unroll
        for (int i = 0; i < 16; i++) {
            const float4 k4 = *(const float4*)&Ks[s][i*4];
            a = fmaf(q[i].x, k4.x, a); a = fmaf(q[i].y, k4.y, a);
            a = fmaf(q[i].z, k4.z, a); a = fmaf(q[i].w, k4.w, a);
        }
        mx = fmaxf(mx, a); sm += a;
    }
    Mout[(size_t)bh*LL + l] = mx - sm * (1.0f/128.0f);
}

// ---------------- top-128 per (b,h): iterative argmax -----------------------
__global__ __launch_bounds__(256)
void topk_kernel(const float* __restrict__ Mvals, int* __restrict__ topidx)
{
    const int bh = blockIdx.x;
    __shared__ float vals[LL];
    __shared__ float rv[256];
    __shared__ int   ri[256];
    const int tid = threadIdx.x;
    for (int i = tid; i < LL; i += 256) vals[i] = Mvals[(size_t)bh*LL + i];
    __syncthreads();
    for (int it = 0; it < UU; ++it) {
        float best = -1e38f; int bi = 1 << 30;
        for (int j = tid; j < LL; j += 256) {
            const float v = vals[j];
            if (v > best) { best = v; bi = j; }
        }
        rv[tid] = best; ri[tid] = bi;
        __syncthreads();
        for (int s = 128; s > 0; s >>= 1) {
            if (tid < s) {
                const float v2 = rv[tid+s]; const int i2 = ri[tid+s];
                if (v2 > rv[tid] || (v2 == rv[tid] && i2 < ri[tid])) {
                    rv[tid] = v2; ri[tid] = i2;
                }
            }
            __syncthreads();
        }
        if (tid == 0) { topidx[bh*UU + it] = ri[0]; vals[ri[0]] = -1e38f; }
        __syncthreads();
    }
}

// ---------------- scores = gather(Q,top) @ K^T * scale ----------------------
__global__ __launch_bounds__(256)
void scores_kernel(const float* __restrict__ Q, const float* __restrict__ Kmat,
                   const int* __restrict__ topidx, float* __restrict__ scores)
{
    const int bh = blockIdx.y, b = bh >> 3, h = bh & 7;
    const int lt = blockIdx.x;                 // 0..31
    __shared__ float As[32][132];              // k x u
    __shared__ float Bs[32][132];              // k x l
    const int tid = threadIdx.x;
    const int ty = tid >> 4, tx = tid & 15;
    float acc[8][8];
    #pragma unroll
    for (int i = 0; i < 8; i++)
        #pragma unroll
        for (int j = 0; j < 8; j++) acc[i][j] = 0.f;

    for (int kc = 0; kc < DH; kc += 32) {
        for (int i = tid; i < 128*8; i += 256) {
            const int u = i >> 3, c4 = (i & 7) * 4;
            const int row = topidx[bh*UU + u];
            const float4 v = *(const float4*)
                &Q[((size_t)(b*LL + row))*DD + h*DH + kc + c4];
            As[c4+0][u] = v.x; As[c4+1][u] = v.y; As[c4+2][u] = v.z; As[c4+3][u] = v.w;
        }
        for (int i = tid; i < 128*8; i += 256) {
            const int l = i >> 3, c4 = (i & 7) * 4;
            const float4 v = *(const float4*)
                &Kmat[((size_t)(b*LL + lt*128 + l))*DD + h*DH + kc + c4];
            Bs[c4+0][l] = v.x; Bs[c4+1][l] = v.y; Bs[c4+2][l] = v.z; Bs[c4+3][l] = v.w;
        }
        __syncthreads();
        #pragma unroll
        for (int k = 0; k < 32; k++) {
            float a[8], bb2[8];
            *(float4*)&a[0]  = *(const float4*)&As[k][ty*8];
            *(float4*)&a[4]  = *(const float4*)&As[k][ty*8+4];
            *(float4*)&bb2[0] = *(const float4*)&Bs[k][tx*8];
            *(float4*)&bb2[4] = *(const float4*)&Bs[k][tx*8+4];
            #pragma unroll
            for (int i = 0; i < 8; i++)
                #pragma unroll
                for (int j = 0; j < 8; j++)
                    acc[i][j] = fmaf(a[i], bb2[j], acc[i][j]);
        }
        __syncthreads();
    }
    const float scale = 0.125f;   // 1/sqrt(64)
    #pragma unroll
    for (int i = 0; i < 8; i++) {
        const int u = ty*8 + i;
        float* outp = scores + ((size_t)bh*UU + u)*LL + lt*128 + tx*8;
        #pragma unroll
        for (int j = 0; j < 8; j += 4) {
            float4 c;
            c.x = acc[i][j+0]*scale; c.y = acc[i][j+1]*scale;
            c.z = acc[i][j+2]*scale; c.w = acc[i][j+3]*scale;
            *(float4*)(outp + j) = c;
        }
    }
}

// ---------------- softmax over L per (bh,u) row -----------------------------
__global__ __launch_bounds__(256)
void softmax_kernel(float* __restrict__ scores)
{
    const size_t row = blockIdx.x;
    float* p = scores + row * LL;
    __shared__ float red[256];
    const int tid = threadIdx.x;
    float4 v[4];
    float mx = -1e30f;
    #pragma unroll
    for (int i = 0; i < 4; i++) {
        v[i] = *(const float4*)&p[tid*4 + i*1024];
        mx = fmaxf(mx, fmaxf(fmaxf(v[i].x, v[i].y), fmaxf(v[i].z, v[i].w)));
    }
    red[tid] = mx; __syncthreads();
    for (int s = 128; s > 0; s >>= 1) {
        if (tid < s) red[tid] = fmaxf(red[tid], red[tid+s]);
        __syncthreads();
    }
    mx = red[0]; __syncthreads();
    float sum = 0.f;
    #pragma unroll
    for (int i = 0; i < 4; i++) {
        v[i].x = __expf(v[i].x - mx); v[i].y = __expf(v[i].y - mx);
        v[i].z = __expf(v[i].z - mx); v[i].w = __expf(v[i].w - mx);
        sum += v[i].x + v[i].y + v[i].z + v[i].w;
    }
    red[tid] = sum; __syncthreads();
    for (int s = 128; s > 0; s >>= 1) {
        if (tid < s) red[tid] += red[tid+s];
        __syncthreads();
    }
    const float inv = 1.0f / red[0];
    #pragma unroll
    for (int i = 0; i < 4; i++) {
        v[i].x *= inv; v[i].y *= inv; v[i].z *= inv; v[i].w *= inv;
        *(float4*)&p[tid*4 + i*1024] = v[i];
    }
}

// ---------------- meanV over L per (b,h) ------------------------------------
__global__ __launch_bounds__(256)
void meanv_kernel(const float* __restrict__ V, float* __restrict__ meanV)
{
    const int bh = blockIdx.x, b = bh >> 3, h = bh & 7;
    __shared__ float sm[4][64];
    const int tid = threadIdx.x;
    const int d = tid & 63, p = tid >> 6;
    float s = 0.f;
    for (int l = p; l < LL; l += 4)
        s += V[((size_t)(b*LL + l))*DD + h*DH + d];
    sm[p][d] = s; __syncthreads();
    if (p == 0)
        meanV[bh*DH + d] = (sm[0][d]+sm[1][d]+sm[2][d]+sm[3][d]) * (1.0f/4096.0f);
}

// ---------------- ctx := broadcast(meanV) -----------------------------------
__global__ void fill_ctx(const float* __restrict__ meanV, float* __restrict__ ctx)
{
    const size_t i = (size_t)blockIdx.x * blockDim.x + threadIdx.x;
    if (i >= (size_t)ROWS*DD) return;
    const int d = (int)(i & 511);
    const int b = (int)(i >> 21);
    const int h = d >> 6, dd = d & 63;
    ctx[i] = meanV[(b*HH + h)*DH + dd];
}

// ---------------- partial ctx_top = attn @ V (split-K) ----------------------
__global__ __launch_bounds__(256)
void ctxpart_kernel(const float* __restrict__ scores, const float* __restrict__ V,
                    float* __restrict__ part)
{
    const int bh = blockIdx.x, ks = blockIdx.y;
    const int b = bh >> 3, h = bh & 7;
    __shared__ float As[8][132];   // k x u
    __shared__ float Bs[8][68];    // k x n
    const int tid = threadIdx.x;
    const int ty = tid >> 4, tx = tid & 15;   // u = ty*8.., n = tx*4..
    float acc[8][4];
    #pragma unroll
    for (int i = 0; i < 8; i++)
        #pragma unroll
        for (int j = 0; j < 4; j++) acc[i][j] = 0.f;

    const float* Arow = scores + (size_t)bh*UU*LL;   // [u][l], ld=LL
    const int kbase0 = ks * (LL / KSPLIT);           // 512 per split
    const int ar = tid >> 1, ac = (tid & 1) * 4;
    const int kr = (tid*2) >> 6, cc = (tid*2) & 63;

    for (int it = 0; it < (LL/KSPLIT)/8; ++it) {
        const int kb = kbase0 + it*8;
        const float4 av = *(const float4*)&Arow[(size_t)ar*LL + kb + ac];
        As[ac+0][ar] = av.x; As[ac+1][ar] = av.y;
        As[ac+2][ar] = av.z; As[ac+3][ar] = av.w;
        const float2 bv = *(const float2*)
            &V[((size_t)(b*LL) + kb + kr)*DD + h*DH + cc];
        Bs[kr][cc] = bv.x; Bs[kr][cc+1] = bv.y;
        __syncthreads();
        #pragma unroll
        for (int k = 0; k < 8; k++) {
            float a[8];
            *(float4*)&a[0] = *(const float4*)&As[k][ty*8];
            *(float4*)&a[4] = *(const float4*)&As[k][ty*8+4];
            const float4 b4 = *(const float4*)&Bs[k][tx*4];
            #pragma unroll
            for (int i = 0; i < 8; i++) {
                acc[i][0] = fmaf(a[i], b4.x, acc[i][0]);
                acc[i][1] = fmaf(a[i], b4.y, acc[i][1]);
                acc[i][2] = fmaf(a[i], b4.z, acc[i][2]);
                acc[i][3] = fmaf(a[i], b4.w, acc[i][3]);
            }
        }
        __syncthreads();
    }
    #pragma unroll
    for (int i = 0; i < 8; i++) {
        const int u = ty*8 + i;
        float4 c; c.x = acc[i][0]; c.y = acc[i][1]; c.z = acc[i][2]; c.w = acc[i][3];
        *(float4*)&part[(((size_t)bh*KSPLIT + ks)*UU + u)*DH + tx*4] = c;
    }
}

// ---------------- combine split-K + scatter into ctx ------------------------
__global__ void combine_scatter(const float* __restrict__ part,
                                const int* __restrict__ topidx,
                                float* __restrict__ ctx)
{
    const int idx = blockIdx.x * blockDim.x + threadIdx.x;  // BHN*UU*DH
    if (idx >= BHN*UU*DH) return;
    const int n = idx & 63, u = (idx >> 6) & 127, bh = idx >> 13;
    float s = 0.f;
    #pragma unroll
    for (int ks = 0; ks < KSPLIT; ks++)
        s += part[(((size_t)bh*KSPLIT + ks)*UU + u)*DH + n];
    const int b = bh >> 3, h = bh & 7;
    const int row = topidx[bh*UU + u];
    ctx[((size_t)(b*LL + row))*DD + h*DH + n] = s;
}

// ---------------- layernorm over D=512 rows ---------------------------------
__global__ __launch_bounds__(128)
void ln_kernel(const float* __restrict__ X, const float* __restrict__ g,
               const float* __restrict__ bb, float* __restrict__ Y)
{
    const size_t row = blockIdx.x;
    const float* x = X + row * DD;
    const int tid = threadIdx.x;
    __shared__ float red[128];
    const float4 v = *(const float4*)&x[tid*4];
    red[tid] = v.x + v.y + v.z + v.w; __syncthreads();
    for (int s = 64; s > 0; s >>= 1) {
        if (tid < s) red[tid] += red[tid+s];
        __syncthreads();
    }
    const float m = red[0] * (1.0f/512.0f);
    __syncthreads();
    const float dx = v.x - m, dy = v.y - m, dz = v.z - m, dw = v.w - m;
    red[tid] = dx*dx + dy*dy + dz*dz + dw*dw; __syncthreads();
    for (int s = 64; s > 0; s >>= 1) {
        if (tid < s) red[tid] += red[tid+s];
        __syncthreads();
    }
    const float var = red[0] * (1.0f/512.0f);
    const float rs = rsqrtf(var + 1e-6f);
    const float4 gv = *(const float4*)&g[tid*4];
    const float4 bv = *(const float4*)&bb[tid*4];
    float4 o;
    o.x = dx*rs*gv.x + bv.x; o.y = dy*rs*gv.y + bv.y;
    o.z = dz*rs*gv.z + bv.z; o.w = dw*rs*gv.w + bv.w;
    *(float4*)&Y[row*DD + tid*4] = o;
}

// ---------------- driver -----------------------------------------------------
extern "C" void kernel_launch(void* const* d_in, const int* in_sizes, int n_in,
                              void* d_out, int out_size)
{
    const float* x    = (const float*)d_in[0];
    const float* Wq   = (const float*)d_in[1];
    const float* bq   = (const float*)d_in[2];
    const float* Wk   = (const float*)d_in[3];
    const float* bk   = (const float*)d_in[4];
    const float* Wv   = (const float*)d_in[5];
    const float* bv   = (const float*)d_in[6];
    const float* Wo   = (const float*)d_in[7];
    const float* bo   = (const float*)d_in[8];
    const float* g1   = (const float*)d_in[9];
    const float* b1   = (const float*)d_in[10];
    const float* W1f  = (const float*)d_in[11];
    const float* b1f  = (const float*)d_in[12];
    const float* W2f  = (const float*)d_in[13];
    const float* b2f  = (const float*)d_in[14];
    const float* g2   = (const float*)d_in[15];
    const float* b2   = (const float*)d_in[16];
    const long long* sidx = (const long long*)d_in[17];
    float* out = (float*)d_out;

    float *Qb,*Kb,*Vb,*Mb,*Sc,*mv,*ctx,*cp,*r1,*x1,*fh,*r2;
    int* ti;
    cudaGetSymbolAddress((void**)&Qb,  g_Q);
    cudaGetSymbolAddress((void**)&Kb,  g_K);
    cudaGetSymbolAddress((void**)&Vb,  g_V);
    cudaGetSymbolAddress((void**)&Mb,  g_M);
    cudaGetSymbolAddress((void**)&ti,  g_topidx);
    cudaGetSymbolAddress((void**)&Sc,  g_scores);
    cudaGetSymbolAddress((void**)&mv,  g_meanV);
    cudaGetSymbolAddress((void**)&ctx, g_ctx);
    cudaGetSymbolAddress((void**)&cp,  g_ctxpart);
    cudaGetSymbolAddress((void**)&r1,  g_res1);
    cudaGetSymbolAddress((void**)&x1,  g_x1);
    cudaGetSymbolAddress((void**)&fh,  g_ffh);
    cudaGetSymbolAddress((void**)&r2,  g_res2);

    // 1-2: Q/K projections (fp32 — selection-critical)
    sgemm_kernel<<<dim3(DD/128, ROWS/128), 256>>>(x, Wq, bq, nullptr, Qb, ROWS, DD, DD, 0);
    sgemm_kernel<<<dim3(DD/128, ROWS/128), 256>>>(x, Wk, bk, nullptr, Kb, ROWS, DD, DD, 0);
    // 3: V projection (tf32 tensor cores)
    tf32_gemm_kernel<<<dim3(DD/128, ROWS/128), 256>>>(x, Wv, bv, nullptr, Vb, ROWS, DD, DD, 0);
    // 4: sampling metric M
    sampm_kernel<<<dim3(LL/128, BHN), 128>>>(Qb, Kb, sidx, Mb);
    // 5: top-128 indices
    topk_kernel<<<BHN, 256>>>(Mb, ti);
    // 6: scores (gathered Q_top @ K^T * scale)
    scores_kernel<<<dim3(LL/128, BHN), 256>>>(Qb, Kb, ti, Sc);
    // 7: softmax
    softmax_kernel<<<BHN*UU, 256>>>(Sc);
    // 8-9: meanV + broadcast fill
    meanv_kernel<<<BHN, 256>>>(Vb, mv);
    fill_ctx<<<(ROWS*DD + 255)/256, 256>>>(mv, ctx);
    // 10-11: attn @ V (split-K) + combine/scatter
    ctxpart_kernel<<<dim3(BHN, KSPLIT), 256>>>(Sc, Vb, cp);
    combine_scatter<<<(BHN*UU*DH + 255)/256, 256>>>(cp, ti, ctx);
    // 12: output projection + residual x (tf32)
    tf32_gemm_kernel<<<dim3(DD/128, ROWS/128), 256>>>(ctx, Wo, bo, x, r1, ROWS, DD, DD, 0);
    // 13: LN1
    ln_kernel<<<ROWS, 128>>>(r1, g1, b1, x1);
    // 14: FFN1 + ReLU (tf32)
    tf32_gemm_kernel<<<dim3(DFF/128, ROWS/128), 256>>>(x1, W1f, b1f, nullptr, fh, ROWS, DFF, DD, 1);
    // 15: FFN2 + residual x1 (tf32)
    tf32_gemm_kernel<<<dim3(DD/128, ROWS/128), 256>>>(fh, W2f, b2f, x1, r2, ROWS, DD, DFF, 0);
    // 16: LN2 -> output
    ln_kernel<<<ROWS, 128>>>(r2, g2, b2, out);
}

// round 9
// speedup vs baseline: 1.6577x; 1.0384x over previous
#include <cuda_runtime.h>
#include <cuda_bf16.h>
#include <cstdint>

// Problem constants
#define BB   8
#define LL   4096
#define DD   512
#define DFF  2048
#define HH   8
#define DH   64
#define SK   128
#define UU   128
#define ROWS (BB*LL)        // 32768
#define BHN  (BB*HH)        // 64
#define KSPLIT 8

// ---------------- scratch (device globals: no allocation allowed) ----------
__device__ float g_Q[ROWS*DD];
__device__ float g_K[ROWS*DD];
__device__ float g_V[ROWS*DD];
__device__ float g_M[BHN*LL];
__device__ int   g_topidx[BHN*UU];
__device__ float g_scores[(size_t)BHN*UU*LL];
__device__ float g_meanV[BHN*DH];
__device__ float g_ctx[ROWS*DD];
__device__ float g_ctxpart[(size_t)BHN*KSPLIT*UU*DH];
__device__ float g_res1[ROWS*DD];
__device__ float g_x1[ROWS*DD];
__device__ float g_ffh[(size_t)ROWS*DFF];
__device__ float g_res2[ROWS*DD];

// ---------------- tf32 helpers ---------------------------------------------
__device__ __forceinline__ uint32_t f2tf(float x) {
    uint32_t u;
    asm("cvt.rna.tf32.f32 %0, %1;" : "=r"(u) : "f"(x));
    return u;
}

__device__ __forceinline__ void tfsplit(float x, uint32_t& hi, uint32_t& lo) {
    hi = f2tf(x);
    lo = f2tf(x - __uint_as_float(hi));
}

__device__ __forceinline__ void mma_tf32(float* c,
    uint32_t a0, uint32_t a1, uint32_t a2, uint32_t a3,
    uint32_t b0, uint32_t b1)
{
    asm volatile(
        "mma.sync.aligned.m16n8k8.row.col.f32.tf32.tf32.f32 "
        "{%0,%1,%2,%3},{%4,%5,%6,%7},{%8,%9},{%0,%1,%2,%3};"
        : "+f"(c[0]), "+f"(c[1]), "+f"(c[2]), "+f"(c[3])
        : "r"(a0), "r"(a1), "r"(a2), "r"(a3), "r"(b0), "r"(b1));
}

// ============================================================================
// Fast tf32 GEMM: C = A(MxK)@B(KxN) + bias [+relu] [+resid]
// 128x128 tile, BK=16, 256 threads, DOUBLE-BUFFERED smem (1 sync/iter).
// Warp layout: 2(M) x 4(N); warp tile 64x32 via m16n8k8.
// ============================================================================
__global__ __launch_bounds__(256)
void tf32_gemm_kernel(const float* __restrict__ A, const float* __restrict__ B,
                      const float* __restrict__ bias, const float* __restrict__ resid,
                      float* __restrict__ C, int M, int N, int K, int doRelu)
{
    __shared__ uint2    smA[2][2][128][5];   // [stage][k8-half][m][pair]
    __shared__ uint32_t smB[2][16][132];     // [stage][k][n]

    const int tid  = threadIdx.x;
    const int warp = tid >> 5, lane = tid & 31;
    const int g = lane >> 2, j = lane & 3;
    const int warpM = (warp >> 2) * 64;
    const int warpN = (warp & 3) * 32;
    const int rowBase = blockIdx.y * 128;
    const int colBase = blockIdx.x * 128;

    const int am = tid >> 1, as = tid & 1;
    const float* Ap = A + (size_t)(rowBase + am) * K + as * 8;
    const int bk = tid >> 4, bn = (tid & 15) * 8;
    const float* Bp = B + (size_t)bk * N + colBase + bn;

    float4 ag0 = *(const float4*)(Ap);
    float4 ag1 = *(const float4*)(Ap + 4);
    float4 bg0 = *(const float4*)(Bp);
    float4 bg1 = *(const float4*)(Bp + 4);

    float acc[4][4][4];
    #pragma unroll
    for (int mi = 0; mi < 4; mi++)
        #pragma unroll
        for (int nf = 0; nf < 4; nf++)
            #pragma unroll
            for (int q = 0; q < 4; q++) acc[mi][nf][q] = 0.f;

    const int nIter = K >> 4;

#define FG_STORE(st) do { \
    smA[st][as][am][0] = make_uint2(f2tf(ag0.x), f2tf(ag1.x)); \
    smA[st][as][am][1] = make_uint2(f2tf(ag0.y), f2tf(ag1.y)); \
    smA[st][as][am][2] = make_uint2(f2tf(ag0.z), f2tf(ag1.z)); \
    smA[st][as][am][3] = make_uint2(f2tf(ag0.w), f2tf(ag1.w)); \
    smB[st][bk][bn+0] = f2tf(bg0.x); smB[st][bk][bn+1] = f2tf(bg0.y); \
    smB[st][bk][bn+2] = f2tf(bg0.z); smB[st][bk][bn+3] = f2tf(bg0.w); \
    smB[st][bk][bn+4] = f2tf(bg1.x); smB[st][bk][bn+5] = f2tf(bg1.y); \
    smB[st][bk][bn+6] = f2tf(bg1.z); smB[st][bk][bn+7] = f2tf(bg1.w); \
} while(0)

    FG_STORE(0);
    if (nIter > 1) {
        Ap += 16; Bp += (size_t)16 * N;
        ag0 = *(const float4*)(Ap); ag1 = *(const float4*)(Ap + 4);
        bg0 = *(const float4*)(Bp); bg1 = *(const float4*)(Bp + 4);
    }
    __syncthreads();

    for (int it = 0; it < nIter; ++it) {
        const int st = it & 1;
        #pragma unroll
        for (int s = 0; s < 2; ++s) {
            uint2 afr[4][2];
            uint32_t bfr[4][2];
            #pragma unroll
            for (int mi = 0; mi < 4; mi++) {
                afr[mi][0] = smA[st][s][warpM + mi*16 + g    ][j];
                afr[mi][1] = smA[st][s][warpM + mi*16 + g + 8][j];
            }
            #pragma unroll
            for (int nf = 0; nf < 4; nf++) {
                bfr[nf][0] = smB[st][s*8 + j    ][warpN + nf*8 + g];
                bfr[nf][1] = smB[st][s*8 + j + 4][warpN + nf*8 + g];
            }
            #pragma unroll
            for (int mi = 0; mi < 4; mi++)
                #pragma unroll
                for (int nf = 0; nf < 4; nf++)
                    mma_tf32(acc[mi][nf],
                             afr[mi][0].x, afr[mi][1].x,
                             afr[mi][0].y, afr[mi][1].y,
                             bfr[nf][0], bfr[nf][1]);
        }
        if (it + 1 < nIter) {
            FG_STORE(st ^ 1);
            if (it + 2 < nIter) {
                Ap += 16; Bp += (size_t)16 * N;
                ag0 = *(const float4*)(Ap); ag1 = *(const float4*)(Ap + 4);
                bg0 = *(const float4*)(Bp); bg1 = *(const float4*)(Bp + 4);
            }
        }
        __syncthreads();
    }
#undef FG_STORE

    #pragma unroll
    for (int mi = 0; mi < 4; mi++) {
        const int row0 = rowBase + warpM + mi*16 + g;
        const int row1 = row0 + 8;
        #pragma unroll
        for (int nf = 0; nf < 4; nf++) {
            const int col = colBase + warpN + nf*8 + j*2;
            const float2 bv = *(const float2*)&bias[col];
            float2 v0, v1;
            v0.x = acc[mi][nf][0] + bv.x; v0.y = acc[mi][nf][1] + bv.y;
            v1.x = acc[mi][nf][2] + bv.x; v1.y = acc[mi][nf][3] + bv.y;
            if (doRelu) {
                v0.x = fmaxf(v0.x, 0.f); v0.y = fmaxf(v0.y, 0.f);
                v1.x = fmaxf(v1.x, 0.f); v1.y = fmaxf(v1.y, 0.f);
            }
            if (resid) {
                const float2 r0 = *(const float2*)&resid[(size_t)row0*N + col];
                const float2 r1 = *(const float2*)&resid[(size_t)row1*N + col];
                v0.x += r0.x; v0.y += r0.y;
                v1.x += r1.x; v1.y += r1.y;
            }
            *(float2*)&C[(size_t)row0*N + col] = v0;
            *(float2*)&C[(size_t)row1*N + col] = v1;
        }
    }
}

// ============================================================================
// Precise 3xTF32 GEMM (error-compensated, ~fp32 accuracy) for Q/K projections.
// C = A@B + bias. 128x128 tile, BK=16, 256 threads, single-buffered.
// ============================================================================
__global__ __launch_bounds__(256)
void tf32x3_gemm_kernel(const float* __restrict__ A, const float* __restrict__ B,
                        const float* __restrict__ bias, float* __restrict__ C,
                        int M, int N, int K)
{
    __shared__ uint4    smA[2][128][5];    // (big_k, big_k4, small_k, small_k4)
    __shared__ uint32_t smBb[16][132];
    __shared__ uint32_t smBs[16][132];

    const int tid  = threadIdx.x;
    const int warp = tid >> 5, lane = tid & 31;
    const int g = lane >> 2, j = lane & 3;
    const int warpM = (warp >> 2) * 64;
    const int warpN = (warp & 3) * 32;
    const int rowBase = blockIdx.y * 128;
    const int colBase = blockIdx.x * 128;

    const int am = tid >> 1, as = tid & 1;
    const float* Ap = A + (size_t)(rowBase + am) * K + as * 8;
    const int bk = tid >> 4, bn = (tid & 15) * 8;
    const float* Bp = B + (size_t)bk * N + colBase + bn;

    float4 ag0 = *(const float4*)(Ap);
    float4 ag1 = *(const float4*)(Ap + 4);
    float4 bg0 = *(const float4*)(Bp);
    float4 bg1 = *(const float4*)(Bp + 4);

    float acc[4][4][4];
    #pragma unroll
    for (int mi = 0; mi < 4; mi++)
        #pragma unroll
        for (int nf = 0; nf < 4; nf++)
            #pragma unroll
            for (int q = 0; q < 4; q++) acc[mi][nf][q] = 0.f;

    const int nIter = K >> 4;
    for (int it = 0; it < nIter; ++it) {
        {
            uint32_t h0,l0,h4,l4;
            tfsplit(ag0.x,h0,l0); tfsplit(ag1.x,h4,l4);
            smA[as][am][0] = make_uint4(h0,h4,l0,l4);
            tfsplit(ag0.y,h0,l0); tfsplit(ag1.y,h4,l4);
            smA[as][am][1] = make_uint4(h0,h4,l0,l4);
            tfsplit(ag0.z,h0,l0); tfsplit(ag1.z,h4,l4);
            smA[as][am][2] = make_uint4(h0,h4,l0,l4);
            tfsplit(ag0.w,h0,l0); tfsplit(ag1.w,h4,l4);
            smA[as][am][3] = make_uint4(h0,h4,l0,l4);
            uint32_t hb, lb;
            tfsplit(bg0.x,hb,lb); smBb[bk][bn+0]=hb; smBs[bk][bn+0]=lb;
            tfsplit(bg0.y,hb,lb); smBb[bk][bn+1]=hb; smBs[bk][bn+1]=lb;
            tfsplit(bg0.z,hb,lb); smBb[bk][bn+2]=hb; smBs[bk][bn+2]=lb;
            tfsplit(bg0.w,hb,lb); smBb[bk][bn+3]=hb; smBs[bk][bn+3]=lb;
            tfsplit(bg1.x,hb,lb); smBb[bk][bn+4]=hb; smBs[bk][bn+4]=lb;
            tfsplit(bg1.y,hb,lb); smBb[bk][bn+5]=hb; smBs[bk][bn+5]=lb;
            tfsplit(bg1.z,hb,lb); smBb[bk][bn+6]=hb; smBs[bk][bn+6]=lb;
            tfsplit(bg1.w,hb,lb); smBb[bk][bn+7]=hb; smBs[bk][bn+7]=lb;
        }
        __syncthreads();

        if (it + 1 < nIter) {
            Ap += 16; Bp += (size_t)16 * N;
            ag0 = *(const float4*)(Ap); ag1 = *(const float4*)(Ap + 4);
            bg0 = *(const float4*)(Bp); bg1 = *(const float4*)(Bp + 4);
        }

        #pragma unroll
        for (int s = 0; s < 2; ++s) {
            uint4 afr[4][2];
            uint32_t bb[4][2], bs[4][2];
            #pragma unroll
            for (int mi = 0; mi < 4; mi++) {
                afr[mi][0] = smA[s][warpM + mi*16 + g    ][j];
                afr[mi][1] = smA[s][warpM + mi*16 + g + 8][j];
            }
            #pragma unroll
            for (int nf = 0; nf < 4; nf++) {
                bb[nf][0] = smBb[s*8 + j    ][warpN + nf*8 + g];
                bb[nf][1] = smBb[s*8 + j + 4][warpN + nf*8 + g];
                bs[nf][0] = smBs[s*8 + j    ][warpN + nf*8 + g];
                bs[nf][1] = smBs[s*8 + j + 4][warpN + nf*8 + g];
            }
            #pragma unroll
            for (int mi = 0; mi < 4; mi++)
                #pragma unroll
                for (int nf = 0; nf < 4; nf++) {
                    // big*small + small*big first, big*big last (accumulate small terms early)
                    mma_tf32(acc[mi][nf],
                             afr[mi][0].x, afr[mi][1].x, afr[mi][0].y, afr[mi][1].y,
                             bs[nf][0], bs[nf][1]);
                    mma_tf32(acc[mi][nf],
                             afr[mi][0].z, afr[mi][1].z, afr[mi][0].w, afr[mi][1].w,
                             bb[nf][0], bb[nf][1]);
                    mma_tf32(acc[mi][nf],
                             afr[mi][0].x, afr[mi][1].x, afr[mi][0].y, afr[mi][1].y,
                             bb[nf][0], bb[nf][1]);
                }
        }
        __syncthreads();
    }

    #pragma unroll
    for (int mi = 0; mi < 4; mi++) {
        const int row0 = rowBase + warpM + mi*16 + g;
        const int row1 = row0 + 8;
        #pragma unroll
        for (int nf = 0; nf < 4; nf++) {
            const int col = colBase + warpN + nf*8 + j*2;
            const float2 bv = *(const float2*)&bias[col];
            float2 v0, v1;
            v0.x = acc[mi][nf][0] + bv.x; v0.y = acc[mi][nf][1] + bv.y;
            v1.x = acc[mi][nf][2] + bv.x; v1.y = acc[mi][nf][3] + bv.y;
            *(float2*)&C[(size_t)row0*N + col] = v0;
            *(float2*)&C[(size_t)row1*N + col] = v1;
        }
    }
}

// ---------------- sampling metric: M[b,h,l] = max_s(QK_s) - mean_s(QK_s) ----
__global__ __launch_bounds__(128)
void sampm_kernel(const float* __restrict__ Q, const float* __restrict__ Kmat,
                  const long long* __restrict__ sidx, float* __restrict__ Mout)
{
    const int bh = blockIdx.y, b = bh >> 3, h = bh & 7;
    const int lt = blockIdx.x;
    __shared__ float Ks[SK][DH];
    const int tid = threadIdx.x;
    for (int i = tid; i < SK*16; i += 128) {
        const int s = i >> 4, c4 = (i & 15) * 4;
        const int row = (int)sidx[s];
        *(float4*)&Ks[s][c4] =
            *(const float4*)&Kmat[((size_t)(b*LL + row))*DD + h*DH + c4];
    }
    __syncthreads();
    const int l = lt*128 + tid;
    float4 q[16];
    const float* qp = &Q[((size_t)(b*LL + l))*DD + h*DH];
    #pragma unroll
    for (int i = 0; i < 16; i++) q[i] = *(const float4*)(qp + i*4);
    float mx = -1e30f, sm = 0.f;
    for (int s = 0; s < SK; s++) {
        float a = 0.f;
        #pragma unroll
        for (int i = 0; i < 16; i++) {
            const float4 k4 = *(const float4*)&Ks[s][i*4];
            a = fmaf(q[i].x, k4.x, a); a = fmaf(q[i].y, k4.y, a);
            a = fmaf(q[i].z, k4.z, a); a = fmaf(q[i].w, k4.w, a);
        }
        mx = fmaxf(mx, a); sm += a;
    }
    Mout[(size_t)bh*LL + l] = mx - sm * (1.0f/128.0f);
}

// ---------------- top-128 per (b,h): iterative argmax -----------------------
__global__ __launch_bounds__(256)
void topk_kernel(const float* __restrict__ Mvals, int* __restrict__ topidx)
{
    const int bh = blockIdx.x;
    __shared__ float vals[LL];
    __shared__ float rv[256];
    __shared__ int   ri[256];
    const int tid = threadIdx.x;
    for (int i = tid; i < LL; i += 256) vals[i] = Mvals[(size_t)bh*LL + i];
    __syncthreads();
    for (int it = 0; it < UU; ++it) {
        float best = -1e38f; int bi = 1 << 30;
        for (int j = tid; j < LL; j += 256) {
            const float v = vals[j];
            if (v > best) { best = v; bi = j; }
        }
        rv[tid] = best; ri[tid] = bi;
        __syncthreads();
        for (int s = 128; s > 0; s >>= 1) {
            if (tid < s) {
                const float v2 = rv[tid+s]; const int i2 = ri[tid+s];
                if (v2 > rv[tid] || (v2 == rv[tid] && i2 < ri[tid])) {
                    rv[tid] = v2; ri[tid] = i2;
                }
            }
            __syncthreads();
        }
        if (tid == 0) { topidx[bh*UU + it] = ri[0]; vals[ri[0]] = -1e38f; }
        __syncthreads();
    }
}

// ============================================================================
// scores = gather(Q,top) @ K^T * scale — tf32 tensor cores.
// Per block: 128(u) x 128(l), K=64 in two 32-wide passes (smem reuse).
// ============================================================================
__global__ __launch_bounds__(256)
void scores_tf32_kernel(const float* __restrict__ Q, const float* __restrict__ Kmat,
                        const int* __restrict__ topidx, float* __restrict__ scores)
{
    const int bh = blockIdx.y, b = bh >> 3, h = bh & 7;
    const int lt = blockIdx.x;
    __shared__ uint2    smA[4][128][5];
    __shared__ uint32_t smB[32][132];
    const int tid = threadIdx.x, warp = tid >> 5, lane = tid & 31;
    const int g = lane >> 2, j = lane & 3;
    const int warpM = (warp >> 2) * 64;
    const int warpN = (warp & 3) * 32;

    float acc[4][4][4];
    #pragma unroll
    for (int mi = 0; mi < 4; mi++)
        #pragma unroll
        for (int nf = 0; nf < 4; nf++)
            #pragma unroll
            for (int q = 0; q < 4; q++) acc[mi][nf][q] = 0.f;

    #pragma unroll
    for (int kc = 0; kc < DH; kc += 32) {
        if (kc) __syncthreads();
        #pragma unroll
        for (int rep = 0; rep < 2; rep++) {
            const int idx = tid + rep*256;       // 0..511
            const int u = idx >> 2, c = idx & 3;
            const int row = topidx[bh*UU + u];
            const float* p = &Q[((size_t)(b*LL + row))*DD + h*DH + kc + c*8];
            const float4 v0 = *(const float4*)p, v1 = *(const float4*)(p+4);
            smA[c][u][0] = make_uint2(f2tf(v0.x), f2tf(v1.x));
            smA[c][u][1] = make_uint2(f2tf(v0.y), f2tf(v1.y));
            smA[c][u][2] = make_uint2(f2tf(v0.z), f2tf(v1.z));
            smA[c][u][3] = make_uint2(f2tf(v0.w), f2tf(v1.w));
        }
        #pragma unroll
        for (int rep = 0; rep < 2; rep++) {
            const int idx = tid + rep*256;
            const int l = idx >> 2, c = idx & 3;
            const float* p = &Kmat[((size_t)(b*LL + lt*128 + l))*DD + h*DH + kc + c*8];
            const float4 v0 = *(const float4*)p, v1 = *(const float4*)(p+4);
            smB[c*8+0][l]=f2tf(v0.x); smB[c*8+1][l]=f2tf(v0.y);
            smB[c*8+2][l]=f2tf(v0.z); smB[c*8+3][l]=f2tf(v0.w);
            smB[c*8+4][l]=f2tf(v1.x); smB[c*8+5][l]=f2tf(v1.y);
            smB[c*8+6][l]=f2tf(v1.z); smB[c*8+7][l]=f2tf(v1.w);
        }
        __syncthreads();
        #pragma unroll
        for (int s = 0; s < 4; ++s) {
            uint2 afr[4][2];
            uint32_t bfr[4][2];
            #pragma unroll
            for (int mi = 0; mi < 4; mi++) {
                afr[mi][0] = smA[s][warpM + mi*16 + g    ][j];
                afr[mi][1] = smA[s][warpM + mi*16 + g + 8][j];
            }
            #pragma unroll
            for (int nf = 0; nf < 4; nf++) {
                bfr[nf][0] = smB[s*8 + j    ][warpN + nf*8 + g];
                bfr[nf][1] = smB[s*8 + j + 4][warpN + nf*8 + g];
            }
            #pragma unroll
            for (int mi = 0; mi < 4; mi++)
                #pragma unroll
                for (int nf = 0; nf < 4; nf++)
                    mma_tf32(acc[mi][nf],
                             afr[mi][0].x, afr[mi][1].x,
                             afr[mi][0].y, afr[mi][1].y,
                             bfr[nf][0], bfr[nf][1]);
        }
    }

    const float scale = 0.125f;
    #pragma unroll
    for (int mi = 0; mi < 4; mi++) {
        const int u0 = warpM + mi*16 + g;
        const int u1 = u0 + 8;
        #pragma unroll
        for (int nf = 0; nf < 4; nf++) {
            const int col = lt*128 + warpN + nf*8 + j*2;
            float2 v0, v1;
            v0.x = acc[mi][nf][0]*scale; v0.y = acc[mi][nf][1]*scale;
            v1.x = acc[mi][nf][2]*scale; v1.y = acc[mi][nf][3]*scale;
            *(float2*)&scores[((size_t)bh*UU + u0)*LL + col] = v0;
            *(float2*)&scores[((size_t)bh*UU + u1)*LL + col] = v1;
        }
    }
}

// ---------------- softmax over L per (bh,u) row -----------------------------
__global__ __launch_bounds__(256)
void softmax_kernel(float* __restrict__ scores)
{
    const size_t row = blockIdx.x;
    float* p = scores + row * LL;
    __shared__ float red[256];
    const int tid = threadIdx.x;
    float4 v[4];
    float mx = -1e30f;
    #pragma unroll
    for (int i = 0; i < 4; i++) {
        v[i] = *(const float4*)&p[tid*4 + i*1024];
        mx = fmaxf(mx, fmaxf(fmaxf(v[i].x, v[i].y), fmaxf(v[i].z, v[i].w)));
    }
    red[tid] = mx; __syncthreads();
    for (int s = 128; s > 0; s >>= 1) {
        if (tid < s) red[tid] = fmaxf(red[tid], red[tid+s]);
        __syncthreads();
    }
    mx = red[0]; __syncthreads();
    float sum = 0.f;
    #pragma unroll
    for (int i = 0; i < 4; i++) {
        v[i].x = __expf(v[i].x - mx); v[i].y = __expf(v[i].y - mx);
        v[i].z = __expf(v[i].z - mx); v[i].w = __expf(v[i].w - mx);
        sum += v[i].x + v[i].y + v[i].z + v[i].w;
    }
    red[tid] = sum; __syncthreads();
    for (int s = 128; s > 0; s >>= 1) {
        if (tid < s) red[tid] += red[tid+s];
        __syncthreads();
    }
    const float inv = 1.0f / red[0];
    #pragma unroll
    for (int i = 0; i < 4; i++) {
        v[i].x *= inv; v[i].y *= inv; v[i].z *= inv; v[i].w *= inv;
        *(float4*)&p[tid*4 + i*1024] = v[i];
    }
}

// ---------------- meanV over L per (b,h) ------------------------------------
__global__ __launch_bounds__(256)
void meanv_kernel(const float* __restrict__ V, float* __restrict__ meanV)
{
    const int bh = blockIdx.x, b = bh >> 3, h = bh & 7;
    __shared__ float sm[4][64];
    const int tid = threadIdx.x;
    const int d = tid & 63, p = tid >> 6;
    float s = 0.f;
    for (int l = p; l < LL; l += 4)
        s += V[((size_t)(b*LL + l))*DD + h*DH + d];
    sm[p][d] = s; __syncthreads();
    if (p == 0)
        meanV[bh*DH + d] = (sm[0][d]+sm[1][d]+sm[2][d]+sm[3][d]) * (1.0f/4096.0f);
}

// ---------------- ctx := broadcast(meanV) -----------------------------------
__global__ void fill_ctx(const float* __restrict__ meanV, float* __restrict__ ctx)
{
    const size_t i = (size_t)blockIdx.x * blockDim.x + threadIdx.x;
    if (i >= (size_t)ROWS*DD) return;
    const int d = (int)(i & 511);
    const int b = (int)(i >> 21);
    const int h = d >> 6, dd = d & 63;
    ctx[i] = meanV[(b*HH + h)*DH + dd];
}

// ============================================================================
// partial ctx_top = attn @ V  (split-K, tf32 tensor cores)
// Per block: 128(u) x 64(dh), K range 512, BK=16, double-buffered.
// Warp layout: 2(M) x 4(N/16); warp tile 64x16.
// ============================================================================
__global__ __launch_bounds__(256)
void ctxpart_tf32_kernel(const float* __restrict__ scores, const float* __restrict__ V,
                         float* __restrict__ part)
{
    const int bh = blockIdx.x, ks = blockIdx.y;
    const int b = bh >> 3, h = bh & 7;
    __shared__ uint2    smA[2][2][128][5];
    __shared__ uint32_t smB[2][16][68];

    const int tid = threadIdx.x, warp = tid >> 5, lane = tid & 31;
    const int g = lane >> 2, j = lane & 3;
    const int warpM = (warp >> 2) * 64;
    const int warpN = (warp & 3) * 16;

    const int am = tid >> 1, as = tid & 1;
    const int bk = tid >> 4, bn = (tid & 15) * 4;
    const int kbase0 = ks * (LL / KSPLIT);
    const float* Ap = scores + ((size_t)bh*UU + am)*LL + kbase0 + as*8;
    const float* Bp = V + ((size_t)(b*LL + kbase0 + bk))*DD + h*DH + bn;

    float4 ag0 = *(const float4*)(Ap);
    float4 ag1 = *(const float4*)(Ap + 4);
    float4 bg  = *(const float4*)(Bp);

    float acc[4][2][4];
    #pragma unroll
    for (int mi = 0; mi < 4; mi++)
        #pragma unroll
        for (int nf = 0; nf < 2; nf++)
            #pragma unroll
            for (int q = 0; q < 4; q++) acc[mi][nf][q] = 0.f;

    const int nIter = (LL / KSPLIT) >> 4;   // 32

#define CP_STORE(st) do { \
    smA[st][as][am][0] = make_uint2(f2tf(ag0.x), f2tf(ag1.x)); \
    smA[st][as][am][1] = make_uint2(f2tf(ag0.y), f2tf(ag1.y)); \
    smA[st][as][am][2] = make_uint2(f2tf(ag0.z), f2tf(ag1.z)); \
    smA[st][as][am][3] = make_uint2(f2tf(ag0.w), f2tf(ag1.w)); \
    smB[st][bk][bn+0] = f2tf(bg.x); smB[st][bk][bn+1] = f2tf(bg.y); \
    smB[st][bk][bn+2] = f2tf(bg.z); smB[st][bk][bn+3] = f2tf(bg.w); \
} while(0)

    CP_STORE(0);
    if (nIter > 1) {
        Ap += 16; Bp += (size_t)16 * DD;
        ag0 = *(const float4*)(Ap); ag1 = *(const float4*)(Ap + 4);
        bg  = *(const float4*)(Bp);
    }
    __syncthreads();

    for (int it = 0; it < nIter; ++it) {
        const int st = it & 1;
        #pragma unroll
        for (int s = 0; s < 2; ++s) {
            uint2 afr[4][2];
            uint32_t bfr[2][2];
            #pragma unroll
            for (int mi = 0; mi < 4; mi++) {
                afr[mi][0] = smA[st][s][warpM + mi*16 + g    ][j];
                afr[mi][1] = smA[st][s][warpM + mi*16 + g + 8][j];
            }
            #pragma unroll
            for (int nf = 0; nf < 2; nf++) {
                bfr[nf][0] = smB[st][s*8 + j    ][warpN + nf*8 + g];
                bfr[nf][1] = smB[st][s*8 + j + 4][warpN + nf*8 + g];
            }
            #pragma unroll
            for (int mi = 0; mi < 4; mi++)
                #pragma unroll
                for (int nf = 0; nf < 2; nf++)
                    mma_tf32(acc[mi][nf],
                             afr[mi][0].x, afr[mi][1].x,
                             afr[mi][0].y, afr[mi][1].y,
                             bfr[nf][0], bfr[nf][1]);
        }
        if (it + 1 < nIter) {
            CP_STORE(st ^ 1);
            if (it + 2 < nIter) {
                Ap += 16; Bp += (size_t)16 * DD;
                ag0 = *(const float4*)(Ap); ag1 = *(const float4*)(Ap + 4);
                bg  = *(const float4*)(Bp);
            }
        }
        __syncthreads();
    }
#undef CP_STORE

    #pragma unroll
    for (int mi = 0; mi < 4; mi++) {
        const int u0 = warpM + mi*16 + g;
        const int u1 = u0 + 8;
        #pragma unroll
        for (int nf = 0; nf < 2; nf++) {
            const int col = warpN + nf*8 + j*2;
            float2 v0, v1;
            v0.x = acc[mi][nf][0]; v0.y = acc[mi][nf][1];
            v1.x = acc[mi][nf][2]; v1.y = acc[mi][nf][3];
            *(float2*)&part[(((size_t)bh*KSPLIT + ks)*UU + u0)*DH + col] = v0;
            *(float2*)&part[(((size_t)bh*KSPLIT + ks)*UU + u1)*DH + col] = v1;
        }
    }
}

// ---------------- combine split-K + scatter into ctx ------------------------
__global__ void combine_scatter(const float* __restrict__ part,
                                const int* __restrict__ topidx,
                                float* __restrict__ ctx)
{
    const int idx = blockIdx.x * blockDim.x + threadIdx.x;  // BHN*UU*DH
    if (idx >= BHN*UU*DH) return;
    const int n = idx & 63, u = (idx >> 6) & 127, bh = idx >> 13;
    float s = 0.f;
    #pragma unroll
    for (int ks = 0; ks < KSPLIT; ks++)
        s += part[(((size_t)bh*KSPLIT + ks)*UU + u)*DH + n];
    const int b = bh >> 3, h = bh & 7;
    const int row = topidx[bh*UU + u];
    ctx[((size_t)(b*LL + row))*DD + h*DH + n] = s;
}

// ---------------- layernorm over D=512 rows ---------------------------------
__global__ __launch_bounds__(128)
void ln_kernel(const float* __restrict__ X, const float* __restrict__ g,
               const float* __restrict__ bb, float* __restrict__ Y)
{
    const size_t row = blockIdx.x;
    const float* x = X + row * DD;
    const int tid = threadIdx.x;
    __shared__ float red[128];
    const float4 v = *(const float4*)&x[tid*4];
    red[tid] = v.x + v.y + v.z + v.w; __syncthreads();
    for (int s = 64; s > 0; s >>= 1) {
        if (tid < s) red[tid] += red[tid+s];
        __syncthreads();
    }
    const float m = red[0] * (1.0f/512.0f);
    __syncthreads();
    const float dx = v.x - m, dy = v.y - m, dz = v.z - m, dw = v.w - m;
    red[tid] = dx*dx + dy*dy + dz*dz + dw*dw; __syncthreads();
    for (int s = 64; s > 0; s >>= 1) {
        if (tid < s) red[tid] += red[tid+s];
        __syncthreads();
    }
    const float var = red[0] * (1.0f/512.0f);
    const float rs = rsqrtf(var + 1e-6f);
    const float4 gv = *(const float4*)&g[tid*4];
    const float4 bv = *(const float4*)&bb[tid*4];
    float4 o;
    o.x = dx*rs*gv.x + bv.x; o.y = dy*rs*gv.y + bv.y;
    o.z = dz*rs*gv.z + bv.z; o.w = dw*rs*gv.w + bv.w;
    *(float4*)&Y[row*DD + tid*4] = o;
}

// ---------------- driver -----------------------------------------------------
extern "C" void kernel_launch(void* const* d_in, const int* in_sizes, int n_in,
                              void* d_out, int out_size)
{
    const float* x    = (const float*)d_in[0];
    const float* Wq   = (const float*)d_in[1];
    const float* bq   = (const float*)d_in[2];
    const float* Wk   = (const float*)d_in[3];
    const float* bk   = (const float*)d_in[4];
    const float* Wv   = (const float*)d_in[5];
    const float* bv   = (const float*)d_in[6];
    const float* Wo   = (const float*)d_in[7];
    const float* bo   = (const float*)d_in[8];
    const float* g1   = (const float*)d_in[9];
    const float* b1   = (const float*)d_in[10];
    const float* W1f  = (const float*)d_in[11];
    const float* b1f  = (const float*)d_in[12];
    const float* W2f  = (const float*)d_in[13];
    const float* b2f  = (const float*)d_in[14];
    const float* g2   = (const float*)d_in[15];
    const float* b2   = (const float*)d_in[16];
    const long long* sidx = (const long long*)d_in[17];
    float* out = (float*)d_out;

    float *Qb,*Kb,*Vb,*Mb,*Sc,*mv,*ctx,*cp,*r1,*x1,*fh,*r2;
    int* ti;
    cudaGetSymbolAddress((void**)&Qb,  g_Q);
    cudaGetSymbolAddress((void**)&Kb,  g_K);
    cudaGetSymbolAddress((void**)&Vb,  g_V);
    cudaGetSymbolAddress((void**)&Mb,  g_M);
    cudaGetSymbolAddress((void**)&ti,  g_topidx);
    cudaGetSymbolAddress((void**)&Sc,  g_scores);
    cudaGetSymbolAddress((void**)&mv,  g_meanV);
    cudaGetSymbolAddress((void**)&ctx, g_ctx);
    cudaGetSymbolAddress((void**)&cp,  g_ctxpart);
    cudaGetSymbolAddress((void**)&r1,  g_res1);
    cudaGetSymbolAddress((void**)&x1,  g_x1);
    cudaGetSymbolAddress((void**)&fh,  g_ffh);
    cudaGetSymbolAddress((void**)&r2,  g_res2);

    // 1-2: Q/K projections (3xTF32 — fp32-accurate, selection-critical)
    tf32x3_gemm_kernel<<<dim3(DD/128, ROWS/128), 256>>>(x, Wq, bq, Qb, ROWS, DD, DD);
    tf32x3_gemm_kernel<<<dim3(DD/128, ROWS/128), 256>>>(x, Wk, bk, Kb, ROWS, DD, DD);
    // 3: V projection (fast tf32)
    tf32_gemm_kernel<<<dim3(DD/128, ROWS/128), 256>>>(x, Wv, bv, nullptr, Vb, ROWS, DD, DD, 0);
    // 4: sampling metric M
    sampm_kernel<<<dim3(LL/128, BHN), 128>>>(Qb, Kb, sidx, Mb);
    // 5: top-128 indices
    topk_kernel<<<BHN, 256>>>(Mb, ti);
    // 6: scores (gathered Q_top @ K^T * scale, tf32)
    scores_tf32_kernel<<<dim3(LL/128, BHN), 256>>>(Qb, Kb, ti, Sc);
    // 7: softmax
    softmax_kernel<<<BHN*UU, 256>>>(Sc);
    // 8-9: meanV + broadcast fill
    meanv_kernel<<<BHN, 256>>>(Vb, mv);
    fill_ctx<<<(ROWS*DD + 255)/256, 256>>>(mv, ctx);
    // 10-11: attn @ V (split-K tf32) + combine/scatter
    ctxpart_tf32_kernel<<<dim3(BHN, KSPLIT), 256>>>(Sc, Vb, cp);
    combine_scatter<<<(BHN*UU*DH + 255)/256, 256>>>(cp, ti, ctx);
    // 12: output projection + residual x (tf32)
    tf32_gemm_kernel<<<dim3(DD/128, ROWS/128), 256>>>(ctx, Wo, bo, x, r1, ROWS, DD, DD, 0);
    // 13: LN1
    ln_kernel<<<ROWS, 128>>>(r1, g1, b1, x1);
    // 14: FFN1 + ReLU (tf32)
    tf32_gemm_kernel<<<dim3(DFF/128, ROWS/128), 256>>>(x1, W1f, b1f, nullptr, fh, ROWS, DFF, DD, 1);
    // 15: FFN2 + residual x1 (tf32)
    tf32_gemm_kernel<<<dim3(DD/128, ROWS/128), 256>>>(fh, W2f, b2f, x1, r2, ROWS, DD, DFF, 0);
    // 16: LN2 -> output
    ln_kernel<<<ROWS, 128>>>(r2, g2, b2, out);
}